// round 11
// baseline (speedup 1.0000x reference)
#include <cuda_runtime.h>
#include <cstdint>

#define BATCH       64
#define SIZE        224
#define PIXELS      (SIZE*SIZE)        // 50176
#define DIM         40
#define NUM_CLASSES 10
#define WORDS       (PIXELS/32)        // 1568
#define NCHUNK      28                 // word chunks in main role
#define CW          (WORDS/NCHUNK)     // 56 words per chunk (exact)
#define QPITCH      57                 // gcd(57,32)=1 -> conflict-free strides
#define BPB         4                  // batches per main block
#define NQUAD       (BATCH/BPB)        // 16
#define PPB         128                // pixels per pack block
#define NBP         (PIXELS/PPB)       // 392 pack blocks (bids 0..391: scheduled first)
#define NMAIN       (NCHUNK*NQUAD)     // 448 main blocks
#define NTOT        (NBP+NMAIN)        // 840 total; 6 blocks/SM x 148 = 888 >= 840

// Packed pos sign bits + deterministic partials (every slot written each run).
__device__ uint32_t g_Q[DIM * WORDS];              // 251 KB
__device__ int      g_TotPart[NCHUNK * DIM];
__device__ int      g_Part[NCHUNK * BATCH * DIM];
__device__ int      g_CPart[NCHUNK * BATCH];
__device__ int      g_FlagP = 0;                   // pack-done counter
__device__ int      g_FlagM = 0;                   // main-done counter (for reset)

// ---------------------------------------------------------------------------
// Fused kernel. Pack role (bid < NBP): pos tile -> smem transpose (pitch 41)
// -> ballots -> STG.128 into g_Q, then threadfence + counter arrive.
// Main role: (1) read x + ballot masks into smem (overlaps pack's DRAM use),
// (2) spin on pack counter, (3) stage Q chunk, (4) AND+popc GEMM -> partials.
// Whole grid is co-resident (launch_bounds(320,6) => 888 slots >= 840), and
// pack blocks never wait => forward progress guaranteed. Last main block
// resets both counters => deterministic across graph replays.
//
// Exactness: pos/level are exactly {-1,+1}; NUM_LEVELS=2 -> idx=round(x) with
// half-to-even so level-1 <=> x>0.5 strictly. All sums to `enc` are exact
// integers in both this kernel and the reference fp32 math.
// ---------------------------------------------------------------------------
__global__ void __launch_bounds__(320, 6)
fused_kernel(const float* __restrict__ x,
             const float* __restrict__ pos) {
    const int tid  = threadIdx.x;
    const int lane = tid & 31;
    const int wid  = tid >> 5;                 // 10 warps

    if (blockIdx.x < NBP) {
        // ================= pack role =================
        __shared__ float tile[PPB * 41];       // 21 KB
        const int p0 = blockIdx.x * PPB;
        const int p  = tid / DIM;              // once
        const int d  = tid - p * DIM;          // once
        const float* __restrict__ src = pos + (size_t)(p0 + p) * DIM + d;
        float* dst = &tile[p * 41 + d];
        #pragma unroll
        for (int k = 0; k < PPB / 8; k++)      // 16 coalesced loads/thread
            dst[k * (8 * 41)] = src[k * (8 * DIM)];
        __syncthreads();

        #pragma unroll
        for (int k = 0; k < 4; k++) {          // warp packs 4 dims x 4 words
            int dd = wid * 4 + k;
            unsigned q0 = __ballot_sync(0xffffffffu, tile[lane * 41 + dd]        > 0.0f);
            unsigned q1 = __ballot_sync(0xffffffffu, tile[(32 + lane) * 41 + dd] > 0.0f);
            unsigned q2 = __ballot_sync(0xffffffffu, tile[(64 + lane) * 41 + dd] > 0.0f);
            unsigned q3 = __ballot_sync(0xffffffffu, tile[(96 + lane) * 41 + dd] > 0.0f);
            if (lane == 0)                     // p0/32 multiple of 4 -> 16B-aligned
                *reinterpret_cast<uint4*>(&g_Q[dd * WORDS + (p0 >> 5)]) =
                    make_uint4(q0, q1, q2, q3);
        }
        __threadfence();                       // writers fence before arrive
        __syncthreads();
        if (tid == 0) atomicAdd(&g_FlagP, 1);
    } else {
        // ================= main role =================
        const int mb = blockIdx.x - NBP;
        const int c  = mb >> 4;                // chunk 0..27
        const int bq = mb & 15;
        const int b0 = bq * BPB;

        __shared__ uint32_t sQ[DIM * QPITCH];  // 9.1 KB
        __shared__ uint32_t sM[BPB][CW];       // 0.9 KB mask words
        __shared__ int sAcc[BPB][DIM];
        __shared__ int sC[BPB];

        if (tid < DIM) {
            #pragma unroll
            for (int i = 0; i < BPB; i++) sAcc[i][tid] = 0;
        }
        if (tid < BPB) sC[tid] = 0;

        const int w0 = c * CW;
        int cc[BPB] = {0, 0, 0, 0};
        // Phase 1: x-ballot (needs no Q) — overlaps pack blocks' DRAM traffic.
        if (wid < 8) {
            const float* __restrict__ xb = x + (size_t)b0 * PIXELS + (size_t)w0 * 32;
            const int jbase = wid * (CW / 8);  // 7 words/warp
            #pragma unroll
            for (int jj = 0; jj < CW / 8; jj++) {
                int j = jbase + jj;
                #pragma unroll
                for (int i = 0; i < BPB; i++) {
                    float v = xb[(size_t)i * PIXELS + j * 32 + lane]; // 128B coalesced
                    unsigned m = __ballot_sync(0xffffffffu, v > 0.5f);
                    cc[i] += __popc(m);
                    if (lane == 0) sM[i][j] = m;
                }
            }
        }

        // Phase 2: wait for all pack blocks (usually already done).
        if (tid == 0) {
            volatile int* fp = &g_FlagP;
            while (*fp != NBP) { }
        }
        __syncthreads();

        // Phase 3: stage Q chunk (uint4, all 10 warps).
        for (int i = tid; i < DIM * (CW / 4); i += 320) {
            int d = i / (CW / 4), j4 = i - d * (CW / 4);
            uint4 v = *reinterpret_cast<const uint4*>(&g_Q[d * WORDS + w0 + j4 * 4]);
            uint32_t* q = &sQ[d * QPITCH + j4 * 4];
            q[0] = v.x; q[1] = v.y; q[2] = v.z; q[3] = v.w;
        }
        __syncthreads();

        // Phase 4: AND+popc GEMM, per-lane dim accumulators.
        if (wid < 8) {
            const int jbase = wid * (CW / 8);
            int aLo[BPB] = {0, 0, 0, 0};
            int aHi[BPB] = {0, 0, 0, 0};
            #pragma unroll
            for (int jj = 0; jj < CW / 8; jj++) {
                int j = jbase + jj;
                uint32_t q0 = sQ[lane * QPITCH + j];            // dim = lane
                #pragma unroll
                for (int i = 0; i < BPB; i++) aLo[i] += __popc(sM[i][j] & q0);
                if (lane < 8) {
                    uint32_t q1 = sQ[(lane + 32) * QPITCH + j]; // dims 32..39
                    #pragma unroll
                    for (int i = 0; i < BPB; i++) aHi[i] += __popc(sM[i][j] & q1);
                }
            }
            #pragma unroll
            for (int i = 0; i < BPB; i++) {
                atomicAdd(&sAcc[i][lane], aLo[i]);
                if (lane < 8) atomicAdd(&sAcc[i][lane + 32], aHi[i]);
                if (lane == 0) atomicAdd(&sC[i], cc[i]);
            }
            // Tot partials from resident sQ (28 bq==0 blocks).
            if (bq == 0) {
                #pragma unroll
                for (int k = 0; k < DIM / 8; k++) {
                    int d = wid + 8 * k;
                    int t = 0;
                    for (int j = lane; j < CW; j += 32)
                        t += __popc(sQ[d * QPITCH + j]);
                    t = __reduce_add_sync(0xffffffffu, t);
                    if (lane == 0) g_TotPart[c * DIM + d] = t;
                }
            }
        }
        __syncthreads();

        if (tid < DIM) {
            #pragma unroll
            for (int i = 0; i < BPB; i++)
                g_Part[(c * BATCH + b0 + i) * DIM + tid] = sAcc[i][tid];
        }
        if (tid < BPB) g_CPart[c * BATCH + b0 + tid] = sC[tid];

        __threadfence();
        __syncthreads();
        if (tid == 0) {
            int done = atomicAdd(&g_FlagM, 1);
            if (done == NMAIN - 1) {           // last main block: reset for next replay
                g_FlagP = 0;
                g_FlagM = 0;
                __threadfence();
            }
        }
    }
}

// ---------------------------------------------------------------------------
// Epilogue: 64 blocks (one per batch). Chunk-sum + exact integer epilogue +
// sign + classify.
// ---------------------------------------------------------------------------
__global__ void __launch_bounds__(64)
epilogue_kernel(const float* __restrict__ lvl,   // [2, DIM]
                const float* __restrict__ cls,   // [10, DIM]
                float* __restrict__ out) {       // [BATCH, 10]
    const int b   = blockIdx.x;
    const int tid = threadIdx.x;
    __shared__ float enc[DIM];
    __shared__ int   sCsum;

    if (tid == 0) {
        int s = 0;
        #pragma unroll
        for (int c = 0; c < NCHUNK; c++) s += g_CPart[c * BATCH + b];
        sCsum = s;
    }
    __syncthreads();

    if (tid < DIM) {
        int sA = 0, sT = 0;
        #pragma unroll
        for (int c = 0; c < NCHUNK; c++) {
            sA += g_Part[(c * BATCH + b) * DIM + tid];
            sT += g_TotPart[c * DIM + tid];
        }
        int A   = 2 * sA - sCsum;           // sum of pos over masked pixels
        int Tot = 2 * sT - PIXELS;          // sum of pos over all pixels
        float summed = lvl[tid] * (float)(Tot - A) + lvl[DIM + tid] * (float)A;
        enc[tid] = (summed > 0.0f) ? 1.0f : -1.0f;
    }
    __syncthreads();

    if (tid < NUM_CLASSES) {
        float acc = 0.0f;
        #pragma unroll
        for (int d = 0; d < DIM; d++) acc += enc[d] * cls[tid * DIM + d];
        out[b * NUM_CLASSES + tid] = acc;
    }
}

// ---------------------------------------------------------------------------
extern "C" void kernel_launch(void* const* d_in, const int* in_sizes, int n_in,
                              void* d_out, int out_size) {
    const float* x   = (const float*)d_in[0];   // [64, 224, 224]
    const float* pos = (const float*)d_in[1];   // [50176, 40]
    const float* lvl = (const float*)d_in[2];   // [2, 40]
    const float* cls = (const float*)d_in[3];   // [10, 40]
    float* out = (float*)d_out;                 // [64, 10]

    fused_kernel<<<NTOT, 320>>>(x, pos);
    epilogue_kernel<<<BATCH, 64>>>(lvl, cls, out);
}